// round 7
// baseline (speedup 1.0000x reference)
#include <cuda_runtime.h>
#include <cstdint>

// Problem dims (fixed by reference)
#define BB 256
#define TT 1024
#define DD 64
#define HH 128
#define NB 2     // batches per scan CTA

typedef unsigned long long ull;

static constexpr size_t BT  = (size_t)BB * TT;        // 262144
static constexpr size_t BTH = (size_t)BB * TT * HH;   // 33554432

// Interleaved scratch: (gate_x_K, tanh(gate_x_z)) per (b,t,h). No cudaMalloc allowed.
__device__ float2 g_gz[BTH + 4 * HH];

// ---- packed f32x2 helpers ----
__device__ __forceinline__ void fma2(ull& acc, ull a, ull b) {
    asm("fma.rn.f32x2 %0, %1, %2, %0;" : "+l"(acc) : "l"(a), "l"(b));
}
__device__ __forceinline__ void add2(ull& a, ull b) {
    asm("add.rn.f32x2 %0, %0, %1;" : "+l"(a) : "l"(b));
}
__device__ __forceinline__ float2 unpk(ull v) {
    float2 f;
    asm("mov.b64 {%0, %1}, %2;" : "=f"(f.x), "=f"(f.y) : "l"(v));
    return f;
}
__device__ __forceinline__ float frcp(float x) {
    float r;
    asm("rcp.approx.f32 %0, %1;" : "=f"(r) : "f"(x));
    return r;
}
// Overflow-safe fast tanh: tanh(x) = sign(x) * (1-e)/(1+e), e = exp(-2|x|)
__device__ __forceinline__ float fast_tanh(float x) {
    float a = fabsf(x);
    float e = __expf(-2.0f * a);
    float t = (1.0f - e) * frcp(1.0f + e);
    return copysignf(t, x);
}
__device__ __forceinline__ float fast_sigmoid(float x) {
    return frcp(1.0f + __expf(-x));
}

// ---------------------------------------------------------------------------
// Kernel 1: input projections. Each CTA: 64 rows of x; thread i = h-index i.
// (unchanged; measured ~237us)
// ---------------------------------------------------------------------------
__global__ void __launch_bounds__(128)
proj_kernel(const float* __restrict__ x,
            const float* __restrict__ WxK, const float* __restrict__ bxK,
            const float* __restrict__ Wxz, const float* __restrict__ bxz)
{
    constexpr int ROWS = 64;
    __shared__ __align__(16) float xs[ROWS * DD];   // 16 KB

    const int i = threadIdx.x;                       // h index 0..127
    const size_t row0 = (size_t)blockIdx.x * ROWS;

    const float4* xg  = (const float4*)(x + row0 * DD);
    float4*       xs4 = (float4*)xs;
#pragma unroll
    for (int k = 0; k < 8; k++) xs4[i + 128 * k] = xg[i + 128 * k];

    ulonglong2 wK[16], wz[16];
    {
        const ulonglong2* wKr = (const ulonglong2*)(WxK + i * DD);
        const ulonglong2* wzr = (const ulonglong2*)(Wxz + i * DD);
#pragma unroll
        for (int m = 0; m < 16; m++) { wK[m] = wKr[m]; wz[m] = wzr[m]; }
    }
    const float bK = bxK[i];
    const float bz = bxz[i];
    __syncthreads();

    for (int r = 0; r < ROWS; r += 2) {
        const ulonglong2* xr0 = (const ulonglong2*)(xs + r * DD);
        const ulonglong2* xr1 = (const ulonglong2*)(xs + (r + 1) * DD);
        ull aK0 = 0, aK1 = 0, az0 = 0, az1 = 0;
        ull cK0 = 0, cK1 = 0, cz0 = 0, cz1 = 0;
#pragma unroll
        for (int m = 0; m < 16; m++) {
            ulonglong2 xv0 = xr0[m];
            ulonglong2 xv1 = xr1[m];
            fma2(aK0, wK[m].x, xv0.x); fma2(aK1, wK[m].y, xv0.y);
            fma2(az0, wz[m].x, xv0.x); fma2(az1, wz[m].y, xv0.y);
            fma2(cK0, wK[m].x, xv1.x); fma2(cK1, wK[m].y, xv1.y);
            fma2(cz0, wz[m].x, xv1.x); fma2(cz1, wz[m].y, xv1.y);
        }
        add2(aK0, aK1); add2(az0, az1); add2(cK0, cK1); add2(cz0, cz1);
        float2 k0 = unpk(aK0), z0 = unpk(az0);
        float2 k1 = unpk(cK0), z1 = unpk(cz0);

        size_t n0 = (row0 + r) * HH + i;
        size_t n1 = n0 + HH;
        g_gz[n0] = make_float2(k0.x + k0.y + bK, fast_tanh(z0.x + z0.y + bz));
        g_gz[n1] = make_float2(k1.x + k1.y + bK, fast_tanh(z1.x + z1.y + bz));
    }
}

// ---------------------------------------------------------------------------
// Kernel 2: sequential scan, NB=2 batches per CTA for intra-warp ILP.
// 128 threads. Thread tid = 32w + l:
//   - owns h[n][tid] for both batches; stages them in per-warp smem slots.
//   - holds W_hK[{l,l+32,l+64,l+96}][32w:32w+32] as 64 f32x2 (shared by both
//     batches), packed over inputs so broadcast LDS.128 of h feeds fma2
//     directly.
//   - per step: both batches' partial dots interleave (independent chains),
//     one cross-warp reduction barrier, pipelined activations.
// ---------------------------------------------------------------------------
__global__ void __launch_bounds__(128, 1)
scan_kernel(const float* __restrict__ WhK, const float* __restrict__ bhK,
            float* __restrict__ out, int dup)
{
    __shared__ __align__(16) float hstage[2][NB][HH];   // [buf][batch][h]
    __shared__ float P[2][NB][4][HH];                   // [buf][batch][warp][out]

    const int tid = threadIdx.x;
    const int w   = tid >> 5;
    const int l   = tid & 31;

    // Weights: 4 outputs x 32 inputs = 64 f32x2 regs, packed over inputs.
    ull wgt[4][16];
#pragma unroll
    for (int k = 0; k < 4; k++) {
        const ull* row = (const ull*)(WhK + (l + 32 * k) * HH + 32 * w);
#pragma unroll
        for (int m = 0; m < 16; m++) wgt[k][m] = row[m];
    }
    const float bh = bhK[tid];

    const float2* gp[NB];
    float* op[NB];
    float h[NB];
    float2 gz0[NB], gz1[NB];
#pragma unroll
    for (int n = 0; n < NB; n++) {
        int b = blockIdx.x * NB + n;
        gp[n] = g_gz + (size_t)b * TT * HH + tid;
        op[n] = out + (size_t)b * TT * HH + tid;
        h[n] = 0.0f;
        hstage[0][n][tid] = 0.0f;
        gz0[n] = gp[n][0];
        gz1[n] = gp[n][HH];
    }
    __syncwarp();

    int cur = 0;
    for (int t = 0; t < TT; t++) {
        // Partial dots for both batches, interleaved (independent chains).
        ull a[NB][4], ab[NB][4];
#pragma unroll
        for (int n = 0; n < NB; n++)
#pragma unroll
            for (int k = 0; k < 4; k++) { a[n][k] = 0; ab[n][k] = 0; }

#pragma unroll
        for (int m = 0; m < 8; m++) {
#pragma unroll
            for (int n = 0; n < NB; n++) {
                const ulonglong2* hv =
                    (const ulonglong2*)(hstage[cur][n] + 32 * w);
                ulonglong2 hx = hv[m];
                fma2(a[n][0],  wgt[0][2 * m],     hx.x);
                fma2(ab[n][0], wgt[0][2 * m + 1], hx.y);
                fma2(a[n][1],  wgt[1][2 * m],     hx.x);
                fma2(ab[n][1], wgt[1][2 * m + 1], hx.y);
                fma2(a[n][2],  wgt[2][2 * m],     hx.x);
                fma2(ab[n][2], wgt[2][2 * m + 1], hx.y);
                fma2(a[n][3],  wgt[3][2 * m],     hx.x);
                fma2(ab[n][3], wgt[3][2 * m + 1], hx.y);
            }
        }
#pragma unroll
        for (int n = 0; n < NB; n++) {
#pragma unroll
            for (int k = 0; k < 4; k++) {
                add2(a[n][k], ab[n][k]);
                float2 p = unpk(a[n][k]);
                P[cur][n][w][l + 32 * k] = p.x + p.y;   // bank l: conflict-free
            }
        }
        __syncthreads();

        // Reduce partials + activation, both batches (pipelined MUFU chains).
#pragma unroll
        for (int n = 0; n < NB; n++) {
            float s = P[cur][n][0][tid] + P[cur][n][1][tid]
                    + P[cur][n][2][tid] + P[cur][n][3][tid] + bh;
            float kg = fast_sigmoid(gz0[n].x + s);
            h[n] = fast_tanh(h[n] + kg * (gz0[n].y - h[n]));

            gz0[n] = gz1[n];
            if (t + 2 < TT) gz1[n] = gp[n][(size_t)(t + 2) * HH];

            op[n][(size_t)t * HH] = h[n];
            if (dup) op[n][BTH + (size_t)t * HH] = h[n];
        }

        cur ^= 1;
#pragma unroll
        for (int n = 0; n < NB; n++) hstage[cur][n][tid] = h[n];
        __syncwarp();   // warp-private slices: syncwarp suffices
    }
}

// ---------------------------------------------------------------------------
extern "C" void kernel_launch(void* const* d_in, const int* in_sizes, int n_in,
                              void* d_out, int out_size)
{
    const float* x   = (const float*)d_in[0];
    const float* WxK = (const float*)d_in[1];
    const float* bxK = (const float*)d_in[2];
    const float* Wxz = (const float*)d_in[3];
    const float* bxz = (const float*)d_in[4];
    const float* WhK = (const float*)d_in[5];
    const float* bhK = (const float*)d_in[6];
    float* out = (float*)d_out;

    proj_kernel<<<(int)(BT / 64), 128>>>(x, WxK, bxK, Wxz, bxz);

    const int dup = ((size_t)out_size >= 2 * BTH) ? 1 : 0;
    scan_kernel<<<BB / NB, 128>>>(WhK, bhK, out, dup);
}

// round 9
// speedup vs baseline: 1.4934x; 1.4934x over previous
#include <cuda_runtime.h>
#include <cstdint>

// Problem dims (fixed by reference)
#define BB 256
#define TT 1024
#define DD 64
#define HH 128

typedef unsigned long long ull;

static constexpr size_t BT  = (size_t)BB * TT;        // 262144
static constexpr size_t BTH = (size_t)BB * TT * HH;   // 33554432

// Interleaved scratch: (gate_x_K, tanh(gate_x_z)) per (b,t,h). No cudaMalloc.
// Padded 4 rows so the scan prefetch (distance 2) is unconditional.
__device__ float2 g_gz[BTH + 4 * HH];

// ---- packed f32x2 helpers ----
__device__ __forceinline__ void fma2(ull& acc, ull a, ull b) {
    asm("fma.rn.f32x2 %0, %1, %2, %0;" : "+l"(acc) : "l"(a), "l"(b));
}
__device__ __forceinline__ void add2(ull& a, ull b) {
    asm("add.rn.f32x2 %0, %0, %1;" : "+l"(a) : "l"(b));
}
__device__ __forceinline__ float2 unpk(ull v) {
    float2 f;
    asm("mov.b64 {%0, %1}, %2;" : "=f"(f.x), "=f"(f.y) : "l"(v));
    return f;
}
__device__ __forceinline__ float frcp(float x) {
    float r;
    asm("rcp.approx.f32 %0, %1;" : "=f"(r) : "f"(x));
    return r;
}
// Overflow-safe fast tanh: tanh(x) = sign(x) * (1-e)/(1+e), e = exp(-2|x|)
__device__ __forceinline__ float fast_tanh(float x) {
    float a = fabsf(x);
    float e = __expf(-2.0f * a);
    float t = (1.0f - e) * frcp(1.0f + e);
    return copysignf(t, x);
}
__device__ __forceinline__ float fast_sigmoid(float x) {
    return frcp(1.0f + __expf(-x));
}

// ---------------------------------------------------------------------------
// Kernel 1: input projections. Each CTA: 64 rows of x; thread i = h-index i.
// (unchanged; measured ~237us)
// ---------------------------------------------------------------------------
__global__ void __launch_bounds__(128)
proj_kernel(const float* __restrict__ x,
            const float* __restrict__ WxK, const float* __restrict__ bxK,
            const float* __restrict__ Wxz, const float* __restrict__ bxz)
{
    constexpr int ROWS = 64;
    __shared__ __align__(16) float xs[ROWS * DD];   // 16 KB

    const int i = threadIdx.x;                       // h index 0..127
    const size_t row0 = (size_t)blockIdx.x * ROWS;

    const float4* xg  = (const float4*)(x + row0 * DD);
    float4*       xs4 = (float4*)xs;
#pragma unroll
    for (int k = 0; k < 8; k++) xs4[i + 128 * k] = xg[i + 128 * k];

    ulonglong2 wK[16], wz[16];
    {
        const ulonglong2* wKr = (const ulonglong2*)(WxK + i * DD);
        const ulonglong2* wzr = (const ulonglong2*)(Wxz + i * DD);
#pragma unroll
        for (int m = 0; m < 16; m++) { wK[m] = wKr[m]; wz[m] = wzr[m]; }
    }
    const float bK = bxK[i];
    const float bz = bxz[i];
    __syncthreads();

    for (int r = 0; r < ROWS; r += 2) {
        const ulonglong2* xr0 = (const ulonglong2*)(xs + r * DD);
        const ulonglong2* xr1 = (const ulonglong2*)(xs + (r + 1) * DD);
        ull aK0 = 0, aK1 = 0, az0 = 0, az1 = 0;
        ull cK0 = 0, cK1 = 0, cz0 = 0, cz1 = 0;
#pragma unroll
        for (int m = 0; m < 16; m++) {
            ulonglong2 xv0 = xr0[m];
            ulonglong2 xv1 = xr1[m];
            fma2(aK0, wK[m].x, xv0.x); fma2(aK1, wK[m].y, xv0.y);
            fma2(az0, wz[m].x, xv0.x); fma2(az1, wz[m].y, xv0.y);
            fma2(cK0, wK[m].x, xv1.x); fma2(cK1, wK[m].y, xv1.y);
            fma2(cz0, wz[m].x, xv1.x); fma2(cz1, wz[m].y, xv1.y);
        }
        add2(aK0, aK1); add2(az0, az1); add2(cK0, cK1); add2(cz0, cz1);
        float2 k0 = unpk(aK0), z0 = unpk(az0);
        float2 k1 = unpk(cK0), z1 = unpk(cz0);

        size_t n0 = (row0 + r) * HH + i;
        size_t n1 = n0 + HH;
        g_gz[n0] = make_float2(k0.x + k0.y + bK, fast_tanh(z0.x + z0.y + bz));
        g_gz[n1] = make_float2(k1.x + k1.y + bK, fast_tanh(z1.x + z1.y + bz));
    }
}

// ---------------------------------------------------------------------------
// Kernel 2: sequential scan, FULL-DOT form. One CTA (128 thr) per batch.
// Thread tid computes output tid with a complete 128-input dot:
//   - weights W_hK[tid][0:128] in 64 f32x2 registers (w[k] = floats 2k,2k+1),
//   - h read via 32 broadcast LDS.128 (hstage = 128 floats = 32 ulonglong2;
//     hv[m].x = h[4m..4m+1], hv[m].y = h[4m+2..4m+3] -> weights w[2m],w[2m+1]),
//   - NO cross-warp partial reduction; exactly ONE STS + ONE __syncthreads
//     per step. Prefetch of (gK,z) is unconditional (padded scratch).
// ---------------------------------------------------------------------------
__global__ void __launch_bounds__(128, 2)
scan_kernel(const float* __restrict__ WhK, const float* __restrict__ bhK,
            float* __restrict__ out, int dup)
{
    __shared__ __align__(16) float hstage[2][HH];   // [buf][h index]

    const int tid = threadIdx.x;
    const int b   = blockIdx.x;

    // Full weight row for output tid: 64 f32x2 (packed over inputs).
    ull w[64];
    {
        const ull* wr = (const ull*)(WhK + tid * HH);
#pragma unroll
        for (int m = 0; m < 64; m++) w[m] = wr[m];
    }
    const float bh = bhK[tid];

    const float2* gp = g_gz + (size_t)b * TT * HH + tid;
    float* op  = out + (size_t)b * TT * HH + tid;
    float* op2 = op + BTH;

    float h = 0.0f;
    hstage[0][tid] = 0.0f;
    float2 gz0 = gp[0];
    float2 gz1 = gp[HH];
    gp += 2 * HH;            // points at t+2 row from now on
    __syncthreads();

    int cur = 0;
    for (int t = 0; t < TT; t++) {
        // 32 broadcast LDS.128 feeding 4 independent fma2 chains (depth 16).
        const ulonglong2* hv = (const ulonglong2*)hstage[cur];
        ull a0 = 0, a1 = 0, a2 = 0, a3 = 0;
#pragma unroll
        for (int m = 0; m < 32; m += 2) {       // 32 ulonglong2 = 128 floats
            ulonglong2 hA = hv[m];
            ulonglong2 hB = hv[m + 1];
            fma2(a0, w[2 * m],     hA.x);
            fma2(a1, w[2 * m + 1], hA.y);
            fma2(a2, w[2 * m + 2], hB.x);
            fma2(a3, w[2 * m + 3], hB.y);
        }
        add2(a0, a2); add2(a1, a3); add2(a0, a1);
        float2 p = unpk(a0);
        float s = p.x + p.y + bh;

        float kg = fast_sigmoid(gz0.x + s);
        h = fast_tanh(h + kg * (gz0.y - h));

        // rotate prefetch (unconditional; scratch is padded)
        gz0 = gz1;
        gz1 = *gp;
        gp += HH;

        op[0] = h;
        if (dup) op2[0] = h;
        op += HH; op2 += HH;

        cur ^= 1;
        hstage[cur][tid] = h;
        __syncthreads();
    }
}

// ---------------------------------------------------------------------------
extern "C" void kernel_launch(void* const* d_in, const int* in_sizes, int n_in,
                              void* d_out, int out_size)
{
    const float* x   = (const float*)d_in[0];
    const float* WxK = (const float*)d_in[1];
    const float* bxK = (const float*)d_in[2];
    const float* Wxz = (const float*)d_in[3];
    const float* bxz = (const float*)d_in[4];
    const float* WhK = (const float*)d_in[5];
    const float* bhK = (const float*)d_in[6];
    float* out = (float*)d_out;

    proj_kernel<<<(int)(BT / 64), 128>>>(x, WxK, bxK, Wxz, bxz);

    const int dup = ((size_t)out_size >= 2 * BTH) ? 1 : 0;
    scan_kernel<<<BB, 128>>>(WhK, bhK, out, dup);
}

// round 10
// speedup vs baseline: 1.5431x; 1.0333x over previous
#include <cuda_runtime.h>
#include <cstdint>

// Problem dims (fixed by reference)
#define BB 256
#define TT 1024
#define DD 64
#define HH 128

typedef unsigned long long ull;

static constexpr size_t BT  = (size_t)BB * TT;        // 262144
static constexpr size_t BTH = (size_t)BB * TT * HH;   // 33554432

// Interleaved scratch: (gate_x_K, tanh(gate_x_z)) per (b,t,h). No cudaMalloc.
// Padded 4 rows so the scan prefetch (distance 3) is unconditional.
__device__ float2 g_gz[BTH + 4 * HH];

// ---- packed f32x2 helpers ----
__device__ __forceinline__ void fma2(ull& acc, ull a, ull b) {
    asm("fma.rn.f32x2 %0, %1, %2, %0;" : "+l"(acc) : "l"(a), "l"(b));
}
__device__ __forceinline__ void add2(ull& a, ull b) {
    asm("add.rn.f32x2 %0, %0, %1;" : "+l"(a) : "l"(b));
}
__device__ __forceinline__ float2 unpk(ull v) {
    float2 f;
    asm("mov.b64 {%0, %1}, %2;" : "=f"(f.x), "=f"(f.y) : "l"(v));
    return f;
}
// Hardware tanh (MUFU.TANH): rel err ~2^-11, single op.
__device__ __forceinline__ float tanh_hw(float x) {
    float r;
    asm("tanh.approx.f32 %0, %1;" : "=f"(r) : "f"(x));
    return r;
}
// sigmoid(x) = 0.5 + 0.5*tanh(x/2)
__device__ __forceinline__ float sigmoid_hw(float x) {
    return fmaf(0.5f, tanh_hw(0.5f * x), 0.5f);
}

// ---------------------------------------------------------------------------
// Kernel 1: input projections. Each CTA: 64 rows of x; thread i = h-index i.
// ---------------------------------------------------------------------------
__global__ void __launch_bounds__(128)
proj_kernel(const float* __restrict__ x,
            const float* __restrict__ WxK, const float* __restrict__ bxK,
            const float* __restrict__ Wxz, const float* __restrict__ bxz)
{
    constexpr int ROWS = 64;
    __shared__ __align__(16) float xs[ROWS * DD];   // 16 KB

    const int i = threadIdx.x;                       // h index 0..127
    const size_t row0 = (size_t)blockIdx.x * ROWS;

    const float4* xg  = (const float4*)(x + row0 * DD);
    float4*       xs4 = (float4*)xs;
#pragma unroll
    for (int k = 0; k < 8; k++) xs4[i + 128 * k] = xg[i + 128 * k];

    ulonglong2 wK[16], wz[16];
    {
        const ulonglong2* wKr = (const ulonglong2*)(WxK + i * DD);
        const ulonglong2* wzr = (const ulonglong2*)(Wxz + i * DD);
#pragma unroll
        for (int m = 0; m < 16; m++) { wK[m] = wKr[m]; wz[m] = wzr[m]; }
    }
    const float bK = bxK[i];
    const float bz = bxz[i];
    __syncthreads();

    for (int r = 0; r < ROWS; r += 2) {
        const ulonglong2* xr0 = (const ulonglong2*)(xs + r * DD);
        const ulonglong2* xr1 = (const ulonglong2*)(xs + (r + 1) * DD);
        ull aK0 = 0, aK1 = 0, az0 = 0, az1 = 0;
        ull cK0 = 0, cK1 = 0, cz0 = 0, cz1 = 0;
#pragma unroll
        for (int m = 0; m < 16; m++) {
            ulonglong2 xv0 = xr0[m];
            ulonglong2 xv1 = xr1[m];
            fma2(aK0, wK[m].x, xv0.x); fma2(aK1, wK[m].y, xv0.y);
            fma2(az0, wz[m].x, xv0.x); fma2(az1, wz[m].y, xv0.y);
            fma2(cK0, wK[m].x, xv1.x); fma2(cK1, wK[m].y, xv1.y);
            fma2(cz0, wz[m].x, xv1.x); fma2(cz1, wz[m].y, xv1.y);
        }
        add2(aK0, aK1); add2(az0, az1); add2(cK0, cK1); add2(cz0, cz1);
        float2 k0 = unpk(aK0), z0 = unpk(az0);
        float2 k1 = unpk(cK0), z1 = unpk(cz0);

        size_t n0 = (row0 + r) * HH + i;
        size_t n1 = n0 + HH;
        g_gz[n0] = make_float2(k0.x + k0.y + bK, tanh_hw(z0.x + z0.y + bz));
        g_gz[n1] = make_float2(k1.x + k1.y + bK, tanh_hw(z1.x + z1.y + bz));
    }
}

// ---------------------------------------------------------------------------
// Kernel 2: sequential scan, FULL-DOT form. One CTA (128 thr) per batch.
// Thread tid computes output tid with a complete 128-input dot:
//   - W_hK[tid][0:128] in 64 f32x2 registers (w[k] = floats 2k,2k+1),
//   - h via 32 broadcast LDS.128 (hstage = 128 floats = 32 ulonglong2),
//   - 8 accumulators (depth-8 fma2 chains) + tree reduce,
//   - activations via single MUFU.TANH each,
//   - ONE STS + ONE __syncthreads per step; unconditional prefetch depth 3.
// ---------------------------------------------------------------------------
__global__ void __launch_bounds__(128, 2)
scan_kernel(const float* __restrict__ WhK, const float* __restrict__ bhK,
            float* __restrict__ out, int dup)
{
    __shared__ __align__(16) float hstage[2][HH];   // [buf][h index]

    const int tid = threadIdx.x;
    const int b   = blockIdx.x;

    // Full weight row for output tid: 64 f32x2 (packed over inputs).
    ull w[64];
    {
        const ull* wr = (const ull*)(WhK + tid * HH);
#pragma unroll
        for (int m = 0; m < 64; m++) w[m] = wr[m];
    }
    const float bh = bhK[tid];

    const float2* gp = g_gz + (size_t)b * TT * HH + tid;
    float* op  = out + (size_t)b * TT * HH + tid;
    float* op2 = op + BTH;

    float h = 0.0f;
    hstage[0][tid] = 0.0f;
    float2 gz0 = gp[0];
    float2 gz1 = gp[HH];
    float2 gz2 = gp[2 * HH];
    gp += 3 * HH;            // points at t+3 row from now on
    __syncthreads();

    int cur = 0;
    for (int t = 0; t < TT; t++) {
        // 32 broadcast LDS.128 feeding 8 independent fma2 chains (depth 8).
        const ulonglong2* hv = (const ulonglong2*)hstage[cur];
        ull a0 = 0, a1 = 0, a2 = 0, a3 = 0, a4 = 0, a5 = 0, a6 = 0, a7 = 0;
#pragma unroll
        for (int m = 0; m < 32; m += 4) {      // 32 ulonglong2 = 128 floats
            ulonglong2 hA = hv[m];
            ulonglong2 hB = hv[m + 1];
            ulonglong2 hC = hv[m + 2];
            ulonglong2 hD = hv[m + 3];
            fma2(a0, w[2 * m],     hA.x);
            fma2(a1, w[2 * m + 1], hA.y);
            fma2(a2, w[2 * m + 2], hB.x);
            fma2(a3, w[2 * m + 3], hB.y);
            fma2(a4, w[2 * m + 4], hC.x);
            fma2(a5, w[2 * m + 5], hC.y);
            fma2(a6, w[2 * m + 6], hD.x);
            fma2(a7, w[2 * m + 7], hD.y);
        }
        add2(a0, a4); add2(a1, a5); add2(a2, a6); add2(a3, a7);
        add2(a0, a2); add2(a1, a3); add2(a0, a1);
        float2 p = unpk(a0);
        float s = p.x + p.y + bh;

        float kg = sigmoid_hw(gz0.x + s);
        h = tanh_hw(fmaf(kg, gz0.y - h, h));

        // rotate prefetch (unconditional; scratch is padded)
        gz0 = gz1;
        gz1 = gz2;
        gz2 = *gp;
        gp += HH;

        op[0] = h;
        if (dup) op2[0] = h;
        op += HH; op2 += HH;

        cur ^= 1;
        hstage[cur][tid] = h;
        __syncthreads();
    }
}

// ---------------------------------------------------------------------------
extern "C" void kernel_launch(void* const* d_in, const int* in_sizes, int n_in,
                              void* d_out, int out_size)
{
    const float* x   = (const float*)d_in[0];
    const float* WxK = (const float*)d_in[1];
    const float* bxK = (const float*)d_in[2];
    const float* Wxz = (const float*)d_in[3];
    const float* bxz = (const float*)d_in[4];
    const float* WhK = (const float*)d_in[5];
    const float* bhK = (const float*)d_in[6];
    float* out = (float*)d_out;

    proj_kernel<<<(int)(BT / 64), 128>>>(x, WxK, bxK, Wxz, bxz);

    const int dup = ((size_t)out_size >= 2 * BTH) ? 1 : 0;
    scan_kernel<<<BB, 128>>>(WhK, bhK, out, dup);
}

// round 11
// speedup vs baseline: 1.7156x; 1.1118x over previous
#include <cuda_runtime.h>
#include <cstdint>

// Problem dims (fixed by reference)
#define BB 256
#define TT 1024
#define DD 64
#define HH 128
#define GRP 2   // batches per scan CTA (separate thread groups + named barriers)

typedef unsigned long long ull;

static constexpr size_t BT  = (size_t)BB * TT;        // 262144
static constexpr size_t BTH = (size_t)BB * TT * HH;   // 33554432

// Interleaved scratch: (gate_x_K, tanh(gate_x_z)) per (b,t,h). No cudaMalloc.
// Padded 4 rows so the scan prefetch (distance 3) is unconditional.
__device__ float2 g_gz[BTH + 4 * HH];

// ---- packed f32x2 helpers ----
__device__ __forceinline__ void fma2(ull& acc, ull a, ull b) {
    asm("fma.rn.f32x2 %0, %1, %2, %0;" : "+l"(acc) : "l"(a), "l"(b));
}
__device__ __forceinline__ void add2(ull& a, ull b) {
    asm("add.rn.f32x2 %0, %0, %1;" : "+l"(a) : "l"(b));
}
__device__ __forceinline__ float2 unpk(ull v) {
    float2 f;
    asm("mov.b64 {%0, %1}, %2;" : "=f"(f.x), "=f"(f.y) : "l"(v));
    return f;
}
// Hardware tanh (MUFU.TANH): rel err ~2^-11, single op.
__device__ __forceinline__ float tanh_hw(float x) {
    float r;
    asm("tanh.approx.f32 %0, %1;" : "=f"(r) : "f"(x));
    return r;
}
// sigmoid(x) = 0.5 + 0.5*tanh(x/2)
__device__ __forceinline__ float sigmoid_hw(float x) {
    return fmaf(0.5f, tanh_hw(0.5f * x), 0.5f);
}

// ---------------------------------------------------------------------------
// Kernel 1: input projections. Each CTA: 64 rows of x; thread i = h-index i.
// (unchanged; ~225us)
// ---------------------------------------------------------------------------
__global__ void __launch_bounds__(128)
proj_kernel(const float* __restrict__ x,
            const float* __restrict__ WxK, const float* __restrict__ bxK,
            const float* __restrict__ Wxz, const float* __restrict__ bxz)
{
    constexpr int ROWS = 64;
    __shared__ __align__(16) float xs[ROWS * DD];   // 16 KB

    const int i = threadIdx.x;                       // h index 0..127
    const size_t row0 = (size_t)blockIdx.x * ROWS;

    const float4* xg  = (const float4*)(x + row0 * DD);
    float4*       xs4 = (float4*)xs;
#pragma unroll
    for (int k = 0; k < 8; k++) xs4[i + 128 * k] = xg[i + 128 * k];

    ulonglong2 wK[16], wz[16];
    {
        const ulonglong2* wKr = (const ulonglong2*)(WxK + i * DD);
        const ulonglong2* wzr = (const ulonglong2*)(Wxz + i * DD);
#pragma unroll
        for (int m = 0; m < 16; m++) { wK[m] = wKr[m]; wz[m] = wzr[m]; }
    }
    const float bK = bxK[i];
    const float bz = bxz[i];
    __syncthreads();

    for (int r = 0; r < ROWS; r += 2) {
        const ulonglong2* xr0 = (const ulonglong2*)(xs + r * DD);
        const ulonglong2* xr1 = (const ulonglong2*)(xs + (r + 1) * DD);
        ull aK0 = 0, aK1 = 0, az0 = 0, az1 = 0;
        ull cK0 = 0, cK1 = 0, cz0 = 0, cz1 = 0;
#pragma unroll
        for (int m = 0; m < 16; m++) {
            ulonglong2 xv0 = xr0[m];
            ulonglong2 xv1 = xr1[m];
            fma2(aK0, wK[m].x, xv0.x); fma2(aK1, wK[m].y, xv0.y);
            fma2(az0, wz[m].x, xv0.x); fma2(az1, wz[m].y, xv0.y);
            fma2(cK0, wK[m].x, xv1.x); fma2(cK1, wK[m].y, xv1.y);
            fma2(cz0, wz[m].x, xv1.x); fma2(cz1, wz[m].y, xv1.y);
        }
        add2(aK0, aK1); add2(az0, az1); add2(cK0, cK1); add2(cz0, cz1);
        float2 k0 = unpk(aK0), z0 = unpk(az0);
        float2 k1 = unpk(cK0), z1 = unpk(cz0);

        size_t n0 = (row0 + r) * HH + i;
        size_t n1 = n0 + HH;
        g_gz[n0] = make_float2(k0.x + k0.y + bK, tanh_hw(z0.x + z0.y + bz));
        g_gz[n1] = make_float2(k1.x + k1.y + bK, tanh_hw(z1.x + z1.y + bz));
    }
}

// ---------------------------------------------------------------------------
// Kernel 2: sequential scan. 512-thread CTA = GRP(2) batches x 256 threads.
// Group g = tid>>8 handles batch blockIdx.x*GRP+g with its OWN named barrier
// (bar.sync g+1, 256) -> each SMSP hosts 4 warps from 2 independent barrier
// domains = 4 overlapping instruction streams.
// Within a group, output i = u>>1 is computed by the lane pair (u, u^1):
//   half = u&1 dots h[64*half .. 64*half+63] (32 ull weights, 16 LDS.128),
//   halves combined with one shfl.bfly; both lanes compute the identical
//   activation. Even lane stores out + next h; odd lane stores the dup copy.
// The h stage is padded (+8 floats between halves) so even/odd lanes hit
// disjoint banks. ONE named barrier per step.
// ---------------------------------------------------------------------------
__global__ void __launch_bounds__(512, 1)
scan_kernel(const float* __restrict__ WhK, const float* __restrict__ bhK,
            float* __restrict__ out, int dup)
{
    // h[j] stored at j + 8*(j>=64): halves start at 0 and 72 (bank-disjoint).
    __shared__ __align__(16) float hst[2][GRP][144];

    const int tid  = threadIdx.x;
    const int g    = tid >> 8;        // batch group 0..GRP-1
    const int u    = tid & 255;       // thread index within group
    const int i    = u >> 1;          // output index 0..127
    const int half = u & 1;           // which 64-input half
    const int b    = blockIdx.x * GRP + g;

    // This lane's 64 weights: W_hK[i][64*half .. +64) as 32 f32x2.
    ull w[32];
    {
        const ull* wr = (const ull*)(WhK + i * HH + half * 64);
#pragma unroll
        for (int m = 0; m < 32; m++) w[m] = wr[m];
    }
    const float bh = bhK[i];

    const float2* gp = g_gz + (size_t)b * TT * HH + i;
    float* op  = out + (size_t)b * TT * HH + i;
    float* op2 = op + BTH;

    float h = 0.0f;
    if (half == 0) hst[0][g][i + ((i & 64) >> 3)] = 0.0f;

    float2 gz0 = gp[0];
    float2 gz1 = gp[HH];
    float2 gz2 = gp[2 * HH];
    gp += 3 * HH;

    asm volatile("bar.sync %0, %1;" :: "r"(g + 1), "r"(256) : "memory");

    int cur = 0;
    for (int t = 0; t < TT; t++) {
        // Half-dot: 16 LDS.128 (this half starts at float offset 72*half).
        const ulonglong2* hv = (const ulonglong2*)(hst[cur][g] + 72 * half);
        ull a0 = 0, a1 = 0, a2 = 0, a3 = 0;
#pragma unroll
        for (int m = 0; m < 16; m += 2) {     // 16 ulonglong2 = 64 floats
            ulonglong2 hA = hv[m];
            ulonglong2 hB = hv[m + 1];
            fma2(a0, w[2 * m],     hA.x);
            fma2(a1, w[2 * m + 1], hA.y);
            fma2(a2, w[2 * m + 2], hB.x);
            fma2(a3, w[2 * m + 3], hB.y);
        }
        add2(a0, a2); add2(a1, a3); add2(a0, a1);
        float2 p = unpk(a0);
        float s = p.x + p.y;
        s += __shfl_xor_sync(0xFFFFFFFFu, s, 1);   // combine halves
        s += bh;

        // both lanes compute identical activation
        float kg = sigmoid_hw(gz0.x + s);
        h = tanh_hw(fmaf(kg, gz0.y - h, h));

        // rotate prefetch (unconditional; scratch padded)
        gz0 = gz1;
        gz1 = gz2;
        gz2 = *gp;
        gp += HH;

        if (half == 0) op[0] = h;
        else if (dup)  op2[0] = h;
        op += HH; op2 += HH;

        cur ^= 1;
        if (half == 0) hst[cur][g][i + ((i & 64) >> 3)] = h;
        asm volatile("bar.sync %0, %1;" :: "r"(g + 1), "r"(256) : "memory");
    }
}

// ---------------------------------------------------------------------------
extern "C" void kernel_launch(void* const* d_in, const int* in_sizes, int n_in,
                              void* d_out, int out_size)
{
    const float* x   = (const float*)d_in[0];
    const float* WxK = (const float*)d_in[1];
    const float* bxK = (const float*)d_in[2];
    const float* Wxz = (const float*)d_in[3];
    const float* bxz = (const float*)d_in[4];
    const float* WhK = (const float*)d_in[5];
    const float* bhK = (const float*)d_in[6];
    float* out = (float*)d_out;

    proj_kernel<<<(int)(BT / 64), 128>>>(x, WxK, bxK, Wxz, bxz);

    const int dup = ((size_t)out_size >= 2 * BTH) ? 1 : 0;
    scan_kernel<<<BB / GRP, 512>>>(WhK, bhK, out, dup);
}